// round 2
// baseline (speedup 1.0000x reference)
#include <cuda_runtime.h>
#include <cuda_bf16.h>

#define G_NUM 1024
#define D 128
#define AS_STRIDE 132   // 128 + 4-float pad, keeps 16B alignment (528B row)

// Scratch (no allocations allowed): segment starts, per-graph context C, W1 transposed.
__device__ int   g_segstart[G_NUM + 1];
__device__ float g_C[G_NUM * D];
__device__ float g_W1t[D * D];

// ---------------------------------------------------------------------------
// K1: per-graph segment boundaries (batch_id is sorted) + transpose W1 so the
// GEMM can load B k-major with fully coalesced LDG and conflict-free STS.
// ---------------------------------------------------------------------------
__global__ void k_prep(const int* __restrict__ bid, int N, const float* __restrict__ W) {
    int t = blockIdx.x * blockDim.x + threadIdx.x;
    if (t < G_NUM) {
        int lo = 0, hi = N;
        while (lo < hi) {
            int mid = (lo + hi) >> 1;
            if (bid[mid] < t) lo = mid + 1; else hi = mid;
        }
        g_segstart[t] = lo;
        if (t == 0) g_segstart[G_NUM] = N;
    }
    // W1t[k*128 + c] = W[c*256 + k]  (W is [128, 256] row-major; W1 = first 128 cols)
    int stride = gridDim.x * blockDim.x;
    for (int i = t; i < D * D; i += stride) {
        int k = i >> 7, c = i & 127;
        g_W1t[i] = W[c * 256 + k];
    }
}

// ---------------------------------------------------------------------------
// K2: one block per graph. 128 threads: thread t owns feature t.
//   mean[g][t] = sum over segment / max(cnt,1)   (coalesced 512B per row)
//   C[g][t]    = b[t] + sum_k mean[g][k] * W[t*256 + 128 + k]
// ---------------------------------------------------------------------------
__global__ void k_mean_ctx(const float* __restrict__ x,
                           const float* __restrict__ W,
                           const float* __restrict__ b) {
    __shared__ float sm[D];
    int g = blockIdx.x;
    int t = threadIdx.x;
    int s = g_segstart[g], e = g_segstart[g + 1];

    float sum = 0.f;
    int n = s;
    for (; n + 4 <= e; n += 4) {
        float v0 = x[(size_t)(n + 0) * D + t];
        float v1 = x[(size_t)(n + 1) * D + t];
        float v2 = x[(size_t)(n + 2) * D + t];
        float v3 = x[(size_t)(n + 3) * D + t];
        sum += (v0 + v1) + (v2 + v3);
    }
    for (; n < e; ++n) sum += x[(size_t)n * D + t];

    int cnt = e - s;
    sm[t] = sum / (float)(cnt > 0 ? cnt : 1);
    __syncthreads();

    float c = b[t];
    const float* wrow = W + (size_t)t * 256 + 128;   // W2 row t, contiguous
#pragma unroll 8
    for (int k = 0; k < D; ++k) c += sm[k] * wrow[k];
    g_C[g * D + t] = c;
}

// ---------------------------------------------------------------------------
// K3: fused GEMM  out[n] = x[n] @ W1^T + C[bid[n]]
// 128x128 tile per CTA, 256 threads, 8x8 per thread, packed f32x2 FMAs.
// ---------------------------------------------------------------------------
__device__ __forceinline__ unsigned long long dup2(float a) {
    unsigned long long r;
    asm("mov.b64 %0, {%1, %1};" : "=l"(r) : "f"(a));
    return r;
}
__device__ __forceinline__ void ffma2(unsigned long long& d,
                                      unsigned long long a,
                                      unsigned long long b) {
    asm("fma.rn.f32x2 %0, %1, %2, %3;" : "=l"(d) : "l"(a), "l"(b), "l"(d));
}

__global__ void __launch_bounds__(256, 1)
k_gemm(const float* __restrict__ x, const int* __restrict__ bid,
       float* __restrict__ out, int N) {
    extern __shared__ float sh[];
    float* As = sh;                        // [128][AS_STRIDE], node-major rows
    float* Bs = sh + 128 * AS_STRIDE;      // [128][AS_STRIDE], k-major rows (from W1t)

    int t = threadIdx.x;
    int n0 = blockIdx.x * 128;

    // Stage A tile: 128 rows x 32 float4 = 4096 vec loads; 256 thr -> 16 iters.
    // Coalesced float4 LDG, contiguous STS (conflict-free).
#pragma unroll
    for (int m = 0; m < 16; ++m) {
        int q = m * 256 + t;
        int node = q >> 5, k4 = q & 31;
        float4 v = make_float4(0.f, 0.f, 0.f, 0.f);
        if (n0 + node < N)
            v = *(const float4*)(x + (size_t)(n0 + node) * 128 + k4 * 4);
        *(float4*)(As + node * AS_STRIDE + k4 * 4) = v;
    }
    // Stage B tile from pre-transposed W1t: same 16 iterations.
#pragma unroll
    for (int m = 0; m < 16; ++m) {
        int q = m * 256 + t;
        int k = q >> 5, c4 = q & 31;
        float4 v = *(const float4*)(g_W1t + k * 128 + c4 * 4);
        *(float4*)(Bs + k * AS_STRIDE + c4 * 4) = v;
    }
    __syncthreads();

    int rg = t >> 4;   // 0..15 -> rows rg*4+{0..3} and +64
    int cg = t & 15;   // 0..15 -> cols cg*4+{0..3} and +64

    const float* a0 = As + (rg * 4) * AS_STRIDE;
    const float* bp = Bs + cg * 4;

    unsigned long long acc[8][4];
#pragma unroll
    for (int i = 0; i < 8; ++i)
#pragma unroll
        for (int j = 0; j < 4; ++j) acc[i][j] = 0ull;

#pragma unroll 8
    for (int k = 0; k < 128; ++k) {
        // B fragment: 2x LDS.128, lanes 0..15 contiguous 256B (conflict-free),
        // halves are natural f32x2 column pairs.
        ulonglong2 bv0 = *(const ulonglong2*)(bp + k * AS_STRIDE);
        ulonglong2 bv1 = *(const ulonglong2*)(bp + k * AS_STRIDE + 64);
#pragma unroll
        for (int i = 0; i < 8; ++i) {
            int row_off = (i < 4) ? i : (64 + i - 4);
            float a = a0[row_off * AS_STRIDE + k];   // broadcast within half-warp
            unsigned long long ad = dup2(a);
            ffma2(acc[i][0], ad, bv0.x);
            ffma2(acc[i][1], ad, bv0.y);
            ffma2(acc[i][2], ad, bv1.x);
            ffma2(acc[i][3], ad, bv1.y);
        }
    }

    // Epilogue: out[n][c] = acc + C[bid[n]][c]
#pragma unroll
    for (int i = 0; i < 8; ++i) {
        int row = rg * 4 + ((i < 4) ? i : (64 + i - 4));
        int n = n0 + row;
        if (n < N) {
            int g = bid[n];
            const float* crow = g_C + g * 128;
#pragma unroll
            for (int h = 0; h < 2; ++h) {
                int c = cg * 4 + h * 64;
                float4 cv = *(const float4*)(crow + c);
                float2 p0 = *(float2*)&acc[i][2 * h + 0];
                float2 p1 = *(float2*)&acc[i][2 * h + 1];
                float4 o = make_float4(p0.x + cv.x, p0.y + cv.y,
                                       p1.x + cv.z, p1.y + cv.w);
                *(float4*)(out + (size_t)n * 128 + c) = o;
            }
        }
    }
}

// ---------------------------------------------------------------------------
extern "C" void kernel_launch(void* const* d_in, const int* in_sizes, int n_in,
                              void* d_out, int out_size) {
    const float* x   = (const float*)d_in[0];
    const int*   bid = (const int*)  d_in[1];
    const float* W   = (const float*)d_in[2];
    const float* b   = (const float*)d_in[3];
    float* out = (float*)d_out;
    int N = in_sizes[1];   // batch_id element count = number of nodes

    const int smem = 2 * 128 * AS_STRIDE * sizeof(float);   // 135168 B
    cudaFuncSetAttribute(k_gemm, cudaFuncAttributeMaxDynamicSharedMemorySize, smem);

    k_prep<<<8, 256>>>(bid, N, W);
    k_mean_ctx<<<G_NUM, 128>>>(x, W, b);
    int grid = (N + 127) / 128;
    k_gemm<<<grid, 256, smem>>>(x, bid, out, N);
}

// round 4
// speedup vs baseline: 1.3346x; 1.3346x over previous
#include <cuda_runtime.h>
#include <cuda_bf16.h>
#include <cstdint>

#define G_NUM 1024
#define D 128

// ---------------------------------------------------------------------------
// Device scratch
// ---------------------------------------------------------------------------
__device__ int   g_segstart[G_NUM + 1];
__device__ float g_C[G_NUM * D];
// W1 in mma.sync B-fragment layout, bf16 hi piece then lo piece.
// Index: ((ks*16 + na)*32 + lane)*2 + reg   (8192 u32 per piece)
__device__ __align__(16) uint32_t g_Bf[2 * 8192];

// ---------------------------------------------------------------------------
// Helpers
// ---------------------------------------------------------------------------
__device__ __forceinline__ uint32_t pack_bf16(float lo, float hi) {
    uint32_t r;
    asm("cvt.rn.bf16x2.f32 %0, %1, %2;" : "=r"(r) : "f"(hi), "f"(lo));
    return r;
}
__device__ __forceinline__ float lo_f(uint32_t p) { return __uint_as_float(p << 16); }
__device__ __forceinline__ float hi_f(uint32_t p) { return __uint_as_float(p & 0xffff0000u); }

__device__ __forceinline__ void mma_bf16(float* d, const uint32_t* a, const uint32_t* b) {
    asm volatile(
        "mma.sync.aligned.m16n8k16.row.col.f32.bf16.bf16.f32 "
        "{%0,%1,%2,%3}, {%4,%5,%6,%7}, {%8,%9}, {%0,%1,%2,%3};"
        : "+f"(d[0]), "+f"(d[1]), "+f"(d[2]), "+f"(d[3])
        : "r"(a[0]), "r"(a[1]), "r"(a[2]), "r"(a[3]), "r"(b[0]), "r"(b[1]));
}

// ---------------------------------------------------------------------------
// K1: segment starts + W1 -> bf16 hi/lo in mma B-fragment layout
// B fragment (m16n8k16 col-major): lane l, group g=l>>2, c=l&3:
//   b0 = { Bmat[k0+2c][n], Bmat[k0+2c+1][n] },  b1 = same with k+8
// where Bmat[k][n] = W1[n][k] = W[n*256 + k], n = na*8 + g, k0 = ks*16.
// ---------------------------------------------------------------------------
__global__ void k_prep(const int* __restrict__ bid, int N, const float* __restrict__ W) {
    int t = blockIdx.x * blockDim.x + threadIdx.x;
    if (t < G_NUM) {
        int lo = 0, hi = N;
        while (lo < hi) {
            int mid = (lo + hi) >> 1;
            if (bid[mid] < t) lo = mid + 1; else hi = mid;
        }
        g_segstart[t] = lo;
        if (t == 0) g_segstart[G_NUM] = N;
    }
    int stride = gridDim.x * blockDim.x;
    for (int i = t; i < 4096; i += stride) {
        int ks = i >> 9;
        int na = (i >> 5) & 15;
        int l  = i & 31;
        int c  = l & 3;
        int n  = na * 8 + (l >> 2);
        int k0 = ks * 16 + 2 * c;
        const float* wr = W + (size_t)n * 256;
        float v00 = wr[k0],     v01 = wr[k0 + 1];
        float v10 = wr[k0 + 8], v11 = wr[k0 + 9];
        uint32_t b0h = pack_bf16(v00, v01);
        uint32_t b1h = pack_bf16(v10, v11);
        uint32_t b0l = pack_bf16(v00 - lo_f(b0h), v01 - hi_f(b0h));
        uint32_t b1l = pack_bf16(v10 - lo_f(b1h), v11 - hi_f(b1h));
        g_Bf[i * 2 + 0]        = b0h;
        g_Bf[i * 2 + 1]        = b1h;
        g_Bf[8192 + i * 2 + 0] = b0l;
        g_Bf[8192 + i * 2 + 1] = b1l;
    }
}

// ---------------------------------------------------------------------------
// K2: per-graph mean + context C[g] = mean[g] @ W2^T + b (fp32 exact)
// ---------------------------------------------------------------------------
__global__ void k_mean_ctx(const float* __restrict__ x,
                           const float* __restrict__ W,
                           const float* __restrict__ b) {
    __shared__ float sm[D];
    int g = blockIdx.x, t = threadIdx.x;
    int s = g_segstart[g], e = g_segstart[g + 1];
    float sum = 0.f;
    int n = s;
    for (; n + 4 <= e; n += 4) {
        float v0 = x[(size_t)(n + 0) * D + t];
        float v1 = x[(size_t)(n + 1) * D + t];
        float v2 = x[(size_t)(n + 2) * D + t];
        float v3 = x[(size_t)(n + 3) * D + t];
        sum += (v0 + v1) + (v2 + v3);
    }
    for (; n < e; ++n) sum += x[(size_t)n * D + t];
    int cnt = e - s;
    sm[t] = sum / (float)(cnt > 0 ? cnt : 1);
    __syncthreads();
    float c = b[t];
    const float* wrow = W + (size_t)t * 256 + 128;
#pragma unroll 8
    for (int k = 0; k < D; ++k) c += sm[k] * wrow[k];
    g_C[g * D + t] = c;
}

// ---------------------------------------------------------------------------
// K3: bf16x3 mma.sync GEMM  out[n] = x[n] @ W1^T + C[bid[n]]
// CTA: 256 thr / 8 warps, tile 256 rows x 128 cols; warp = 32 rows x 128 cols.
// A fragments register-resident (direct gmem fp32 -> bf16 hi/lo).
// ---------------------------------------------------------------------------
#define STG_STRIDE 136                       // floats; kills STS bank conflicts
#define SMEM_BYTES (128 * STG_STRIDE * 4)    // 69632 >= 65536 (B frags)

__global__ void __launch_bounds__(256, 1)
k_gemm(const float* __restrict__ x, const int* __restrict__ bid,
       float* __restrict__ out, int N) {
    extern __shared__ __align__(16) uint32_t sh[];
    uint32_t* shB = sh;                      // [16384] u32: hi(8192) | lo(8192)

    int tid = threadIdx.x;
    int w   = tid >> 5;
    int l   = tid & 31;
    int n0  = blockIdx.x * 256;

    // Stage B fragments: 16384 u32 = 4096 uint4; 16 per thread, coalesced.
#pragma unroll
    for (int i = 0; i < 16; ++i) {
        int q = i * 256 + tid;
        *(uint4*)(shB + q * 4) = *(const uint4*)(g_Bf + q * 4);
    }
    __syncthreads();

    // Per-thread A row bases (m16n8k16 A frag: rows g, g+8 per m-atom)
    int g4 = l >> 2, c4 = l & 3;
    int rbase = n0 + w * 32;
    int r00 = rbase + g4;            // ma=0 rows
    int r01 = r00 + 8;
    int r10 = rbase + 16 + g4;       // ma=1 rows
    int r11 = r10 + 8;
    const float* p00 = x + (size_t)r00 * 128;
    const float* p01 = x + (size_t)r01 * 128;
    const float* p10 = x + (size_t)r10 * 128;
    const float* p11 = x + (size_t)r11 * 128;
    bool v00r = r00 < N, v01r = r01 < N, v10r = r10 < N, v11r = r11 < N;

    float acc[2][16][4];
#pragma unroll
    for (int ma = 0; ma < 2; ++ma)
#pragma unroll
        for (int na = 0; na < 16; ++na)
#pragma unroll
            for (int j = 0; j < 4; ++j) acc[ma][na][j] = 0.f;

    const float2 z2 = make_float2(0.f, 0.f);

    for (int ks = 0; ks < 8; ++ks) {
        int k0 = ks * 16 + 2 * c4;
        // Load A pairs (a0: r0/k0, a1: r1/k0, a2: r0/k0+8, a3: r1/k0+8) per m-atom
        float2 f[2][4];
        f[0][0] = v00r ? *(const float2*)(p00 + k0)     : z2;
        f[0][1] = v01r ? *(const float2*)(p01 + k0)     : z2;
        f[0][2] = v00r ? *(const float2*)(p00 + k0 + 8) : z2;
        f[0][3] = v01r ? *(const float2*)(p01 + k0 + 8) : z2;
        f[1][0] = v10r ? *(const float2*)(p10 + k0)     : z2;
        f[1][1] = v11r ? *(const float2*)(p11 + k0)     : z2;
        f[1][2] = v10r ? *(const float2*)(p10 + k0 + 8) : z2;
        f[1][3] = v11r ? *(const float2*)(p11 + k0 + 8) : z2;

        uint32_t ahi[2][4], alo[2][4];
#pragma unroll
        for (int ma = 0; ma < 2; ++ma)
#pragma unroll
            for (int j = 0; j < 4; ++j) {
                float2 v = f[ma][j];
                uint32_t h = pack_bf16(v.x, v.y);
                ahi[ma][j] = h;
                alo[ma][j] = pack_bf16(v.x - lo_f(h), v.y - hi_f(h));
            }

        const uint32_t* bks = shB + ks * 16 * 64;   // (ks*16+na)*32 lanes *2 regs
#pragma unroll
        for (int na = 0; na < 16; ++na) {
            uint2 bh = *(const uint2*)(bks + na * 64 + l * 2);
            uint2 bl = *(const uint2*)(bks + 8192 + na * 64 + l * 2);
            uint32_t bhr[2] = {bh.x, bh.y};
            uint32_t blr[2] = {bl.x, bl.y};
#pragma unroll
            for (int ma = 0; ma < 2; ++ma) {
                mma_bf16(acc[ma][na], ahi[ma], bhr);   // hi*hi
                mma_bf16(acc[ma][na], alo[ma], bhr);   // lo*hi
                mma_bf16(acc[ma][na], ahi[ma], blr);   // hi*lo
            }
        }
    }

    // --- Epilogue: stage 128 rows at a time through smem, add C, store ---
    float* stg = (float*)sh;
#pragma unroll
    for (int chunk = 0; chunk < 2; ++chunk) {
        __syncthreads();   // previous smem use done (B frags / prior chunk)
        if ((w >> 2) == chunk) {
            int rl_base = (w & 3) * 32;
#pragma unroll
            for (int ma = 0; ma < 2; ++ma) {
                int rl0 = rl_base + ma * 16 + g4;
#pragma unroll
                for (int na = 0; na < 16; ++na) {
                    int cb = na * 8 + 2 * c4;
                    *(float2*)(stg + rl0 * STG_STRIDE + cb) =
                        make_float2(acc[ma][na][0], acc[ma][na][1]);
                    *(float2*)(stg + (rl0 + 8) * STG_STRIDE + cb) =
                        make_float2(acc[ma][na][2], acc[ma][na][3]);
                }
            }
        }
        __syncthreads();
        int cw = l * 4;
#pragma unroll
        for (int it = 0; it < 16; ++it) {
            int rloc = it * 8 + w;
            int n = n0 + chunk * 128 + rloc;
            if (n < N) {
                float4 v = *(float4*)(stg + rloc * STG_STRIDE + cw);
                int gidx = bid[n];
                float4 cv = *(const float4*)(g_C + (size_t)gidx * 128 + cw);
                v.x += cv.x; v.y += cv.y; v.z += cv.z; v.w += cv.w;
                *(float4*)(out + (size_t)n * 128 + cw) = v;
            }
        }
    }
}

// ---------------------------------------------------------------------------
extern "C" void kernel_launch(void* const* d_in, const int* in_sizes, int n_in,
                              void* d_out, int out_size) {
    const float* x   = (const float*)d_in[0];
    const int*   bid = (const int*)  d_in[1];
    const float* W   = (const float*)d_in[2];
    const float* b   = (const float*)d_in[3];
    float* out = (float*)d_out;
    int N = in_sizes[1];

    cudaFuncSetAttribute(k_gemm, cudaFuncAttributeMaxDynamicSharedMemorySize, SMEM_BYTES);

    k_prep<<<16, 256>>>(bid, N, W);
    k_mean_ctx<<<G_NUM, 128>>>(x, W, b);
    int grid = (N + 255) / 256;
    k_gemm<<<grid, 256, SMEM_BYTES>>>(x, bid, out, N);
}

// round 5
// speedup vs baseline: 1.8075x; 1.3543x over previous
#include <cuda_runtime.h>
#include <cuda_bf16.h>
#include <cstdint>

#define G_NUM 1024
#define D 128

// ---------------------------------------------------------------------------
// Device scratch
// ---------------------------------------------------------------------------
__device__ int   g_segstart[G_NUM + 1];
__device__ float g_C[G_NUM * D];
// W1 in mma.sync B-fragment layout, bf16 hi piece then lo piece.
// Index: ((ks*16 + na)*32 + lane)*2 + reg   (8192 u32 per piece)
__device__ __align__(16) uint32_t g_Bf[2 * 8192];

// ---------------------------------------------------------------------------
// Helpers
// ---------------------------------------------------------------------------
__device__ __forceinline__ uint32_t pack_bf16(float lo, float hi) {
    uint32_t r;
    asm("cvt.rn.bf16x2.f32 %0, %1, %2;" : "=r"(r) : "f"(hi), "f"(lo));
    return r;
}
__device__ __forceinline__ float lo_f(uint32_t p) { return __uint_as_float(p << 16); }
__device__ __forceinline__ float hi_f(uint32_t p) { return __uint_as_float(p & 0xffff0000u); }

__device__ __forceinline__ void mma_bf16(float* d, const uint32_t* a, const uint32_t* b) {
    asm volatile(
        "mma.sync.aligned.m16n8k16.row.col.f32.bf16.bf16.f32 "
        "{%0,%1,%2,%3}, {%4,%5,%6,%7}, {%8,%9}, {%0,%1,%2,%3};"
        : "+f"(d[0]), "+f"(d[1]), "+f"(d[2]), "+f"(d[3])
        : "r"(a[0]), "r"(a[1]), "r"(a[2]), "r"(a[3]), "r"(b[0]), "r"(b[1]));
}

// ---------------------------------------------------------------------------
// K1: parallel segment boundaries + W1 -> bf16 hi/lo B-fragments.
// bid is sorted: wherever it steps past g, that index is segstart[g].
// ---------------------------------------------------------------------------
__global__ void k_prep(const int* __restrict__ bid, int N, const float* __restrict__ W) {
    int i = blockIdx.x * blockDim.x + threadIdx.x;
    if (i < N) {
        int b = bid[i];
        int prev = (i == 0) ? -1 : bid[i - 1];
        for (int g = prev + 1; g <= b; ++g) g_segstart[g] = i;
        if (i == N - 1)
            for (int g = b + 1; g <= G_NUM; ++g) g_segstart[g] = N;
    }
    // W fragment packing (4096 fragment slots)
    if (i < 4096) {
        int ks = i >> 9;
        int na = (i >> 5) & 15;
        int l  = i & 31;
        int c  = l & 3;
        int n  = na * 8 + (l >> 2);
        int k0 = ks * 16 + 2 * c;
        const float* wr = W + (size_t)n * 256;
        float v00 = wr[k0],     v01 = wr[k0 + 1];
        float v10 = wr[k0 + 8], v11 = wr[k0 + 9];
        uint32_t b0h = pack_bf16(v00, v01);
        uint32_t b1h = pack_bf16(v10, v11);
        uint32_t b0l = pack_bf16(v00 - lo_f(b0h), v01 - hi_f(b0h));
        uint32_t b1l = pack_bf16(v10 - lo_f(b1h), v11 - hi_f(b1h));
        g_Bf[i * 2 + 0]        = b0h;
        g_Bf[i * 2 + 1]        = b1h;
        g_Bf[8192 + i * 2 + 0] = b0l;
        g_Bf[8192 + i * 2 + 1] = b1l;
    }
}

// ---------------------------------------------------------------------------
// K2: per-graph mean (float4 loads, 4-row groups) + C[g] = mean @ W2^T + b
// ---------------------------------------------------------------------------
__global__ void k_mean_ctx(const float* __restrict__ x,
                           const float* __restrict__ W,
                           const float* __restrict__ b) {
    __shared__ float4 sred[128];
    __shared__ float  sm[D];
    int g = blockIdx.x, t = threadIdx.x;
    int s = g_segstart[g], e = g_segstart[g + 1];
    int grp = t >> 5;        // 0..3: row offset within group of 4
    int ln  = t & 31;        // feature quad ln*4

    float4 a0 = make_float4(0.f, 0.f, 0.f, 0.f), a1 = a0, a2 = a0, a3 = a0;
    int n = s + grp;
    for (; n + 12 < e; n += 16) {
        float4 v0 = *(const float4*)(x + (size_t)(n +  0) * D + ln * 4);
        float4 v1 = *(const float4*)(x + (size_t)(n +  4) * D + ln * 4);
        float4 v2 = *(const float4*)(x + (size_t)(n +  8) * D + ln * 4);
        float4 v3 = *(const float4*)(x + (size_t)(n + 12) * D + ln * 4);
        a0.x += v0.x; a0.y += v0.y; a0.z += v0.z; a0.w += v0.w;
        a1.x += v1.x; a1.y += v1.y; a1.z += v1.z; a1.w += v1.w;
        a2.x += v2.x; a2.y += v2.y; a2.z += v2.z; a2.w += v2.w;
        a3.x += v3.x; a3.y += v3.y; a3.z += v3.z; a3.w += v3.w;
    }
    for (; n < e; n += 4) {
        float4 v = *(const float4*)(x + (size_t)n * D + ln * 4);
        a0.x += v.x; a0.y += v.y; a0.z += v.z; a0.w += v.w;
    }
    a0.x += a1.x + a2.x + a3.x; a0.y += a1.y + a2.y + a3.y;
    a0.z += a1.z + a2.z + a3.z; a0.w += a1.w + a2.w + a3.w;
    sred[t] = a0;
    __syncthreads();
    if (grp == 0) {
        float4 u0 = sred[ln], u1 = sred[32 + ln], u2 = sred[64 + ln], u3 = sred[96 + ln];
        int cnt = e - s;
        float inv = 1.f / (float)(cnt > 0 ? cnt : 1);
        sm[ln * 4 + 0] = (u0.x + u1.x + u2.x + u3.x) * inv;
        sm[ln * 4 + 1] = (u0.y + u1.y + u2.y + u3.y) * inv;
        sm[ln * 4 + 2] = (u0.z + u1.z + u2.z + u3.z) * inv;
        sm[ln * 4 + 3] = (u0.w + u1.w + u2.w + u3.w) * inv;
    }
    __syncthreads();
    float c = b[t];
    const float* wrow = W + (size_t)t * 256 + 128;
#pragma unroll 8
    for (int k = 0; k < D; ++k) c += sm[k] * wrow[k];
    g_C[g * D + t] = c;
}

// ---------------------------------------------------------------------------
// K3: bf16x3 mma.sync GEMM  out[n] = x[n] @ W1^T + C[bid[n]]
// CTA: 256 thr / 8 warps, tile 128 rows x 128 cols; warp = 16 rows x 128 cols.
// 2 CTAs/SM, register-prefetched A.
// ---------------------------------------------------------------------------
#define STG_STRIDE 136
#define SMEM_BYTES (128 * STG_STRIDE * 4)   // 69632 >= 65536 (B frags)

__global__ void __launch_bounds__(256, 2)
k_gemm(const float* __restrict__ x, const int* __restrict__ bid,
       float* __restrict__ out, int N) {
    extern __shared__ __align__(16) uint32_t sh[];
    uint32_t* shB = sh;                      // [16384] u32: hi(8192) | lo(8192)

    int tid = threadIdx.x;
    int w   = tid >> 5;
    int l   = tid & 31;
    int n0  = blockIdx.x * 128;

    // Stage B fragments: 4096 uint4, coalesced.
#pragma unroll
    for (int i = 0; i < 16; ++i) {
        int q = i * 256 + tid;
        *(uint4*)(shB + q * 4) = *(const uint4*)(g_Bf + q * 4);
    }
    __syncthreads();

    int g4 = l >> 2, c4 = l & 3;
    int r0 = n0 + w * 16 + g4;
    int r1 = r0 + 8;
    const float* p0 = x + (size_t)r0 * 128;
    const float* p1 = x + (size_t)r1 * 128;
    bool vr0 = r0 < N, vr1 = r1 < N;
    const float2 z2 = make_float2(0.f, 0.f);

    float acc[16][4];
#pragma unroll
    for (int na = 0; na < 16; ++na)
#pragma unroll
        for (int j = 0; j < 4; ++j) acc[na][j] = 0.f;

    // Prefetch ks=0
    float2 cur0, cur1, cur2, cur3;
    {
        int k0 = 2 * c4;
        cur0 = vr0 ? *(const float2*)(p0 + k0)     : z2;
        cur1 = vr1 ? *(const float2*)(p1 + k0)     : z2;
        cur2 = vr0 ? *(const float2*)(p0 + k0 + 8) : z2;
        cur3 = vr1 ? *(const float2*)(p1 + k0 + 8) : z2;
    }

#pragma unroll
    for (int ks = 0; ks < 8; ++ks) {
        float2 nx0, nx1, nx2, nx3;
        if (ks < 7) {
            int k0 = (ks + 1) * 16 + 2 * c4;
            nx0 = vr0 ? *(const float2*)(p0 + k0)     : z2;
            nx1 = vr1 ? *(const float2*)(p1 + k0)     : z2;
            nx2 = vr0 ? *(const float2*)(p0 + k0 + 8) : z2;
            nx3 = vr1 ? *(const float2*)(p1 + k0 + 8) : z2;
        }

        uint32_t ahi[4], alo[4];
        {
            float2 f[4] = {cur0, cur1, cur2, cur3};
#pragma unroll
            for (int j = 0; j < 4; ++j) {
                uint32_t h = pack_bf16(f[j].x, f[j].y);
                ahi[j] = h;
                alo[j] = pack_bf16(f[j].x - lo_f(h), f[j].y - hi_f(h));
            }
        }

        const uint32_t* bks = shB + ks * 16 * 64;
#pragma unroll
        for (int na = 0; na < 16; ++na) {
            uint2 bh = *(const uint2*)(bks + na * 64 + l * 2);
            uint2 bl = *(const uint2*)(bks + 8192 + na * 64 + l * 2);
            uint32_t bhr[2] = {bh.x, bh.y};
            uint32_t blr[2] = {bl.x, bl.y};
            mma_bf16(acc[na], ahi, bhr);   // hi*hi
            mma_bf16(acc[na], alo, bhr);   // lo*hi
            mma_bf16(acc[na], ahi, blr);   // hi*lo
        }
        cur0 = nx0; cur1 = nx1; cur2 = nx2; cur3 = nx3;
    }

    // --- Epilogue: stage through smem (reuses B buffer), add C, store ---
    float* stg = (float*)sh;
    __syncthreads();   // all warps done reading shB
    {
        int rl0 = w * 16 + g4;
#pragma unroll
        for (int na = 0; na < 16; ++na) {
            int cb = na * 8 + 2 * c4;
            *(float2*)(stg + rl0 * STG_STRIDE + cb) =
                make_float2(acc[na][0], acc[na][1]);
            *(float2*)(stg + (rl0 + 8) * STG_STRIDE + cb) =
                make_float2(acc[na][2], acc[na][3]);
        }
    }
    __syncthreads();
    {
        int cw = l * 4;
#pragma unroll
        for (int it = 0; it < 16; ++it) {
            int rloc = it * 8 + w;
            int n = n0 + rloc;
            if (n < N) {
                float4 v = *(float4*)(stg + rloc * STG_STRIDE + cw);
                int gidx = bid[n];
                float4 cv = *(const float4*)(g_C + (size_t)gidx * 128 + cw);
                v.x += cv.x; v.y += cv.y; v.z += cv.z; v.w += cv.w;
                *(float4*)(out + (size_t)n * 128 + cw) = v;
            }
        }
    }
}

// ---------------------------------------------------------------------------
extern "C" void kernel_launch(void* const* d_in, const int* in_sizes, int n_in,
                              void* d_out, int out_size) {
    const float* x   = (const float*)d_in[0];
    const int*   bid = (const int*)  d_in[1];
    const float* W   = (const float*)d_in[2];
    const float* b   = (const float*)d_in[3];
    float* out = (float*)d_out;
    int N = in_sizes[1];

    cudaFuncSetAttribute(k_gemm, cudaFuncAttributeMaxDynamicSharedMemorySize, SMEM_BYTES);

    k_prep<<<(N + 255) / 256, 256>>>(bid, N, W);
    k_mean_ctx<<<G_NUM, 128>>>(x, W, b);
    int grid = (N + 127) / 128;
    k_gemm<<<grid, 256, SMEM_BYTES>>>(x, bid, out, N);
}

// round 6
// speedup vs baseline: 1.9196x; 1.0620x over previous
#include <cuda_runtime.h>
#include <cuda_bf16.h>
#include <cuda_fp16.h>
#include <cstdint>

#define G_NUM 1024
#define D 128

// ---------------------------------------------------------------------------
// Device scratch
// ---------------------------------------------------------------------------
__device__ int   g_segstart[G_NUM + 1];
__device__ float g_C[G_NUM * D];
// W1 (fp16) in mma.sync B-fragment layout: ((ks*16 + na)*32 + lane)*2 + reg
__device__ __align__(16) uint32_t g_Bf[8192];

// ---------------------------------------------------------------------------
// Helpers
// ---------------------------------------------------------------------------
__device__ __forceinline__ uint32_t pack_f16(float lo, float hi) {
    uint32_t r;
    asm("cvt.rn.f16x2.f32 %0, %1, %2;" : "=r"(r) : "f"(hi), "f"(lo));
    return r;
}
__device__ __forceinline__ float lo_h(uint32_t p) {
    return __half2float(__ushort_as_half((unsigned short)(p & 0xffff)));
}
__device__ __forceinline__ float hi_h(uint32_t p) {
    return __half2float(__ushort_as_half((unsigned short)(p >> 16)));
}

__device__ __forceinline__ void mma_f16(float* d, const uint32_t* a, const uint32_t* b) {
    asm volatile(
        "mma.sync.aligned.m16n8k16.row.col.f32.f16.f16.f32 "
        "{%0,%1,%2,%3}, {%4,%5,%6,%7}, {%8,%9}, {%0,%1,%2,%3};"
        : "+f"(d[0]), "+f"(d[1]), "+f"(d[2]), "+f"(d[3])
        : "r"(a[0]), "r"(a[1]), "r"(a[2]), "r"(a[3]), "r"(b[0]), "r"(b[1]));
}

// ---------------------------------------------------------------------------
// K1: parallel segment boundaries + W1 -> fp16 B-fragments
// ---------------------------------------------------------------------------
__global__ void k_prep(const int* __restrict__ bid, int N, const float* __restrict__ W) {
    int i = blockIdx.x * blockDim.x + threadIdx.x;
    if (i < N) {
        int b = bid[i];
        int prev = (i == 0) ? -1 : bid[i - 1];
        for (int g = prev + 1; g <= b; ++g) g_segstart[g] = i;
        if (i == N - 1)
            for (int g = b + 1; g <= G_NUM; ++g) g_segstart[g] = N;
    }
    if (i < 4096) {
        int ks = i >> 9;
        int na = (i >> 5) & 15;
        int l  = i & 31;
        int c  = l & 3;
        int n  = na * 8 + (l >> 2);
        int k0 = ks * 16 + 2 * c;
        const float* wr = W + (size_t)n * 256;
        g_Bf[i * 2 + 0] = pack_f16(wr[k0],     wr[k0 + 1]);
        g_Bf[i * 2 + 1] = pack_f16(wr[k0 + 8], wr[k0 + 9]);
    }
}

// ---------------------------------------------------------------------------
// K2: per-graph mean (float4 loads, 4-row groups) + C[g] = mean @ W2^T + b
// ---------------------------------------------------------------------------
__global__ void k_mean_ctx(const float* __restrict__ x,
                           const float* __restrict__ W,
                           const float* __restrict__ b) {
    __shared__ float4 sred[128];
    __shared__ float  sm[D];
    int g = blockIdx.x, t = threadIdx.x;
    int s = g_segstart[g], e = g_segstart[g + 1];
    int grp = t >> 5;
    int ln  = t & 31;

    float4 a0 = make_float4(0.f, 0.f, 0.f, 0.f), a1 = a0, a2 = a0, a3 = a0;
    int n = s + grp;
    for (; n + 12 < e; n += 16) {
        float4 v0 = *(const float4*)(x + (size_t)(n +  0) * D + ln * 4);
        float4 v1 = *(const float4*)(x + (size_t)(n +  4) * D + ln * 4);
        float4 v2 = *(const float4*)(x + (size_t)(n +  8) * D + ln * 4);
        float4 v3 = *(const float4*)(x + (size_t)(n + 12) * D + ln * 4);
        a0.x += v0.x; a0.y += v0.y; a0.z += v0.z; a0.w += v0.w;
        a1.x += v1.x; a1.y += v1.y; a1.z += v1.z; a1.w += v1.w;
        a2.x += v2.x; a2.y += v2.y; a2.z += v2.z; a2.w += v2.w;
        a3.x += v3.x; a3.y += v3.y; a3.z += v3.z; a3.w += v3.w;
    }
    for (; n < e; n += 4) {
        float4 v = *(const float4*)(x + (size_t)n * D + ln * 4);
        a0.x += v.x; a0.y += v.y; a0.z += v.z; a0.w += v.w;
    }
    a0.x += a1.x + a2.x + a3.x; a0.y += a1.y + a2.y + a3.y;
    a0.z += a1.z + a2.z + a3.z; a0.w += a1.w + a2.w + a3.w;
    sred[t] = a0;
    __syncthreads();
    if (grp == 0) {
        float4 u0 = sred[ln], u1 = sred[32 + ln], u2 = sred[64 + ln], u3 = sred[96 + ln];
        int cnt = e - s;
        float inv = 1.f / (float)(cnt > 0 ? cnt : 1);
        sm[ln * 4 + 0] = (u0.x + u1.x + u2.x + u3.x) * inv;
        sm[ln * 4 + 1] = (u0.y + u1.y + u2.y + u3.y) * inv;
        sm[ln * 4 + 2] = (u0.z + u1.z + u2.z + u3.z) * inv;
        sm[ln * 4 + 3] = (u0.w + u1.w + u2.w + u3.w) * inv;
    }
    __syncthreads();
    float c = b[t];
    const float* wrow = W + (size_t)t * 256 + 128;
#pragma unroll 8
    for (int k = 0; k < D; ++k) c += sm[k] * wrow[k];
    g_C[g * D + t] = c;
}

// ---------------------------------------------------------------------------
// K3: fp16x2 mma.sync GEMM  out[n] = x[n] @ W1^T + C[bid[n]]
// D = (a_hi + a_lo) * b_hi : 2 MMAs per (ks,na), shared B fragment.
// CTA: 256 thr / 8 warps, tile 128x128; warp = 16 rows x 128 cols; 2 CTA/SM.
// ---------------------------------------------------------------------------
#define STG_STRIDE 136
#define SMEM_BYTES (128 * STG_STRIDE * 4)   // 69632 (B frags need only 32KB)

__global__ void __launch_bounds__(256, 2)
k_gemm(const float* __restrict__ x, const int* __restrict__ bid,
       float* __restrict__ out, int N) {
    extern __shared__ __align__(16) uint32_t sh[];
    uint32_t* shB = sh;                      // [8192] u32 fp16 B frags

    int tid = threadIdx.x;
    int w   = tid >> 5;
    int l   = tid & 31;
    int n0  = blockIdx.x * 128;

    // Stage B fragments: 2048 uint4, 256 threads -> 8 iters, coalesced.
#pragma unroll
    for (int i = 0; i < 8; ++i) {
        int q = i * 256 + tid;
        *(uint4*)(shB + q * 4) = *(const uint4*)(g_Bf + q * 4);
    }
    __syncthreads();

    int g4 = l >> 2, c4 = l & 3;
    int r0 = n0 + w * 16 + g4;
    int r1 = r0 + 8;
    const float* p0 = x + (size_t)r0 * 128;
    const float* p1 = x + (size_t)r1 * 128;
    bool full = (n0 + 128) <= N;
    bool vr0 = full || (r0 < N), vr1 = full || (r1 < N);
    const float2 z2 = make_float2(0.f, 0.f);

    float acc[16][4];
#pragma unroll
    for (int na = 0; na < 16; ++na)
#pragma unroll
        for (int j = 0; j < 4; ++j) acc[na][j] = 0.f;

    float2 cur0, cur1, cur2, cur3;
    {
        int k0 = 2 * c4;
        if (full) {
            cur0 = *(const float2*)(p0 + k0);
            cur1 = *(const float2*)(p1 + k0);
            cur2 = *(const float2*)(p0 + k0 + 8);
            cur3 = *(const float2*)(p1 + k0 + 8);
        } else {
            cur0 = vr0 ? *(const float2*)(p0 + k0)     : z2;
            cur1 = vr1 ? *(const float2*)(p1 + k0)     : z2;
            cur2 = vr0 ? *(const float2*)(p0 + k0 + 8) : z2;
            cur3 = vr1 ? *(const float2*)(p1 + k0 + 8) : z2;
        }
    }

#pragma unroll
    for (int ks = 0; ks < 8; ++ks) {
        float2 nx0, nx1, nx2, nx3;
        if (ks < 7) {
            int k0 = (ks + 1) * 16 + 2 * c4;
            if (full) {
                nx0 = *(const float2*)(p0 + k0);
                nx1 = *(const float2*)(p1 + k0);
                nx2 = *(const float2*)(p0 + k0 + 8);
                nx3 = *(const float2*)(p1 + k0 + 8);
            } else {
                nx0 = vr0 ? *(const float2*)(p0 + k0)     : z2;
                nx1 = vr1 ? *(const float2*)(p1 + k0)     : z2;
                nx2 = vr0 ? *(const float2*)(p0 + k0 + 8) : z2;
                nx3 = vr1 ? *(const float2*)(p1 + k0 + 8) : z2;
            }
        }

        uint32_t ahi[4], alo[4];
        {
            float2 f[4] = {cur0, cur1, cur2, cur3};
#pragma unroll
            for (int j = 0; j < 4; ++j) {
                uint32_t h = pack_f16(f[j].x, f[j].y);
                ahi[j] = h;
                alo[j] = pack_f16(f[j].x - lo_h(h), f[j].y - hi_h(h));
            }
        }

        const uint32_t* bks = shB + ks * 16 * 64;
#pragma unroll
        for (int na = 0; na < 16; ++na) {
            uint2 bh = *(const uint2*)(bks + na * 64 + l * 2);
            uint32_t bhr[2] = {bh.x, bh.y};
            mma_f16(acc[na], ahi, bhr);
            mma_f16(acc[na], alo, bhr);
        }
        cur0 = nx0; cur1 = nx1; cur2 = nx2; cur3 = nx3;
    }

    // --- Epilogue: stage through smem, add C, store coalesced ---
    float* stg = (float*)sh;
    __syncthreads();
    {
        int rl0 = w * 16 + g4;
#pragma unroll
        for (int na = 0; na < 16; ++na) {
            int cb = na * 8 + 2 * c4;
            *(float2*)(stg + rl0 * STG_STRIDE + cb) =
                make_float2(acc[na][0], acc[na][1]);
            *(float2*)(stg + (rl0 + 8) * STG_STRIDE + cb) =
                make_float2(acc[na][2], acc[na][3]);
        }
    }
    __syncthreads();
    {
        int cw = l * 4;
#pragma unroll
        for (int it = 0; it < 16; ++it) {
            int rloc = it * 8 + w;
            int n = n0 + rloc;
            if (n < N) {
                float4 v = *(float4*)(stg + rloc * STG_STRIDE + cw);
                int gidx = bid[n];
                float4 cv = *(const float4*)(g_C + (size_t)gidx * 128 + cw);
                v.x += cv.x; v.y += cv.y; v.z += cv.z; v.w += cv.w;
                *(float4*)(out + (size_t)n * 128 + cw) = v;
            }
        }
    }
}

// ---------------------------------------------------------------------------
extern "C" void kernel_launch(void* const* d_in, const int* in_sizes, int n_in,
                              void* d_out, int out_size) {
    const float* x   = (const float*)d_in[0];
    const int*   bid = (const int*)  d_in[1];
    const float* W   = (const float*)d_in[2];
    const float* b   = (const float*)d_in[3];
    float* out = (float*)d_out;
    int N = in_sizes[1];

    cudaFuncSetAttribute(k_gemm, cudaFuncAttributeMaxDynamicSharedMemorySize, SMEM_BYTES);

    k_prep<<<(N + 255) / 256, 256>>>(bid, N, W);
    k_mean_ctx<<<G_NUM, 128>>>(x, W, b);
    int grid = (N + 127) / 128;
    k_gemm<<<grid, 256, SMEM_BYTES>>>(x, bid, out, N);
}